// round 3
// baseline (speedup 1.0000x reference)
#include <cuda_runtime.h>
#include <cuda_fp16.h>

// CostVolumeManager: plane-sweep cost volume.
// B=1, S=8, C=16, H=64, W=96, D=64.
// Strategy:
//   pass 1: transpose src_feats [S,C,H,W] -> fp16 [S,H*W,C]  (channel-contiguous, 32B/pixel)
//   pass 2: transpose cur_feats [C,H,W]   -> fp32 [H*W,C]
//   pass 3: one thread per (x, d): project through all 8 sources, 4 bilinear taps,
//           each tap = 2x LDG.128 of fp16 channels, dot vs cur in fp32.
// Warp = 32 consecutive x at fixed (y, d) -> taps slide smoothly along source rows
// -> high L1 line reuse. Whole source set (1.6 MB fp16) is L2-resident.

namespace cvk {

constexpr int S = 8, C = 16, H = 64, W = 96, D = 64, N = H * W;

// Scratch (static device globals; no allocation).
__device__ uint4  g_src[S * N * 2];  // fp16 [s][n][c], 32B per pixel (2 x uint4)
__device__ float4 g_cur[N * 4];      // fp32 [n][c], 64B per pixel

__global__ void pack_src(const float* __restrict__ src) {
    int idx = blockIdx.x * 256 + threadIdx.x;   // s*N + n
    if (idx >= S * N) return;
    int s = idx / N, n = idx - s * N;
    const float* p = src + (size_t)s * C * N + n;
    unsigned w[8];
#pragma unroll
    for (int j = 0; j < 8; j++) {
        float a = p[(size_t)(2 * j) * N];       // coalesced across lanes
        float b = p[(size_t)(2 * j + 1) * N];
        __half2 h = __floats2half2_rn(a, b);
        w[j] = *reinterpret_cast<unsigned*>(&h);
    }
    g_src[idx * 2 + 0] = make_uint4(w[0], w[1], w[2], w[3]);
    g_src[idx * 2 + 1] = make_uint4(w[4], w[5], w[6], w[7]);
}

__global__ void pack_cur(const float* __restrict__ cur) {
    int n = blockIdx.x * 256 + threadIdx.x;
    if (n >= N) return;
#pragma unroll
    for (int q = 0; q < 4; q++) {
        float4 f;
        f.x = cur[(size_t)(4 * q + 0) * N + n];
        f.y = cur[(size_t)(4 * q + 1) * N + n];
        f.z = cur[(size_t)(4 * q + 2) * N + n];
        f.w = cur[(size_t)(4 * q + 3) * N + n];
        g_cur[n * 4 + q] = f;
    }
}

__device__ __forceinline__ float dot16(const uint4 a, const uint4 b,
                                       const float* __restrict__ cf) {
    float s = 0.f;
    float2 f;
#define CVK_ACC(word, i0)                                              \
    {                                                                  \
        __half2 h = *reinterpret_cast<const __half2*>(&(word));        \
        f = __half22float2(h);                                         \
        s += f.x * cf[i0] + f.y * cf[(i0) + 1];                        \
    }
    CVK_ACC(a.x, 0)  CVK_ACC(a.y, 2)  CVK_ACC(a.z, 4)  CVK_ACC(a.w, 6)
    CVK_ACC(b.x, 8)  CVK_ACC(b.y, 10) CVK_ACC(b.z, 12) CVK_ACC(b.w, 14)
#undef CVK_ACC
    return s;
}

__device__ __forceinline__ float tap(int sbase, int xi, int yi, float w,
                                     const float* __restrict__ cf) {
    // grid_sample zeros-padding semantics: clip index, zero the weight if OOB.
    float valid = (xi >= 0 && xi < W && yi >= 0 && yi < H) ? 1.f : 0.f;
    int xc = min(max(xi, 0), W - 1);
    int yc = min(max(yi, 0), H - 1);
    const uint4* sp = g_src + (size_t)(sbase + yc * W + xc) * 2;
    uint4 a = sp[0];
    uint4 b = sp[1];
    return dot16(a, b, cf) * (w * valid);
}

__global__ __launch_bounds__(256)
void cost_main(const float* __restrict__ exts, const float* __restrict__ Ks,
               const float* __restrict__ invK, const float* __restrict__ mnp,
               const float* __restrict__ mxp, float* __restrict__ out) {
    // Per-block: P[s] = (Ks[s] @ exts[s]) rows 0..2  (8 x 12 floats in smem)
    __shared__ float sP[S][12];
    int t = threadIdx.y * 32 + threadIdx.x;
    if (t < S * 12) {
        int s = t / 12, rc = t - 12 * s, r = rc >> 2, c = rc & 3;
        float acc = 0.f;
#pragma unroll
        for (int k = 0; k < 4; k++)
            acc += Ks[s * 16 + r * 4 + k] * exts[s * 16 + k * 4 + c];
        sP[s][rc] = acc;
    }
    __syncthreads();

    int x = blockIdx.x * 32 + threadIdx.x;
    int y = blockIdx.y;
    int d = blockIdx.z * 8 + threadIdx.y;
    int n = y * W + x;

    // Log-spaced depth bin (matches jnp.linspace(0,1,64): ramp = d/63)
    float mnv = mnp[0], mxv = mxp[0];
    float depth = expf(logf(mnv) + logf(mxv / mnv) * ((float)d * (1.f / 63.f)));

    // Back-projected ray * depth
    float pxc = (float)x + 0.5f, pyc = (float)y + 0.5f;
    float X = depth * (invK[0] * pxc + invK[1] * pyc + invK[2]);
    float Y = depth * (invK[4] * pxc + invK[5] * pyc + invK[6]);
    float Z = depth * (invK[8] * pxc + invK[9] * pyc + invK[10]);

    // Current-frame feature vector in registers
    float cf[16];
#pragma unroll
    for (int q = 0; q < 4; q++) {
        float4 f = g_cur[n * 4 + q];
        cf[4 * q + 0] = f.x; cf[4 * q + 1] = f.y;
        cf[4 * q + 2] = f.z; cf[4 * q + 3] = f.w;
    }

    float cost = 0.f;
#pragma unroll
    for (int s = 0; s < S; s++) {
        const float* P = sP[s];
        float pu = P[0] * X + P[1] * Y + P[2]  * Z + P[3];
        float pv = P[4] * X + P[5] * Y + P[6]  * Z + P[7];
        float pz = P[8] * X + P[9] * Y + P[10] * Z + P[11];
        float iz = 1.f / (pz + 1e-8f);
        float gx = pu * iz - 0.5f;
        float gy = pv * iz - 0.5f;
        float x0f = floorf(gx), y0f = floorf(gy);
        float wx = gx - x0f, wy = gy - y0f;
        int x0 = (int)x0f, y0 = (int)y0f;
        int sbase = s * N;
        float a = tap(sbase, x0,     y0,     (1.f - wx) * (1.f - wy), cf)
                + tap(sbase, x0 + 1, y0,     wx         * (1.f - wy), cf)
                + tap(sbase, x0,     y0 + 1, (1.f - wx) * wy,         cf)
                + tap(sbase, x0 + 1, y0 + 1, wx         * wy,         cf);
        cost += (pz > 0.f) ? a : 0.f;   // mask = (z > 0)
    }

    out[d * N + n] = cost;              // cost_volume [D,H,W]
    out[D * N + d * N + n] = depth;     // depth_planes [D,H,W]
}

}  // namespace cvk

extern "C" void kernel_launch(void* const* d_in, const int* in_sizes, int n_in,
                              void* d_out, int out_size) {
    using namespace cvk;
    const float* cur  = (const float*)d_in[0];  // [1,16,64,96]
    const float* src  = (const float*)d_in[1];  // [1,8,16,64,96]
    const float* exts = (const float*)d_in[2];  // [1,8,4,4]
    const float* Ks   = (const float*)d_in[3];  // [1,8,4,4]
    const float* invK = (const float*)d_in[4];  // [1,4,4]
    const float* mnp  = (const float*)d_in[5];  // [1,1,1,1]
    const float* mxp  = (const float*)d_in[6];  // [1,1,1,1]
    float* out = (float*)d_out;                 // cost_volume ++ depth_planes

    pack_src<<<(S * N + 255) / 256, 256>>>(src);
    pack_cur<<<(N + 255) / 256, 256>>>(cur);

    dim3 blk(32, 8);
    dim3 grd(W / 32, H, D / 8);
    cost_main<<<grd, blk>>>(exts, Ks, invK, mnp, mxp, out);
}

// round 4
// speedup vs baseline: 1.2914x; 1.2914x over previous
#include <cuda_runtime.h>
#include <cuda_fp16.h>

// CostVolumeManager: plane-sweep cost volume. B=1, S=8, C=16, H=64, W=96, D=64.
//
// v3 strategy (L1-wavefront-bound fix):
//   - src features packed fp16 into TWO channel-split planes, 16B/pixel each
//     (ch0-7 in plane A, ch8-15 in plane B). Halves the lane stride of tap
//     loads -> each warp LDG.128 touches ~4-5 L1 lines instead of ~8-9.
//   - bilinear weights (with zeros-padding validity folded in) applied as an
//     fp16 HFMA2 blend of the 4 taps; blended vector converted once and dotted
//     against the current-frame features with packed fma.rn.f32x2, accumulating
//     across taps AND sources in one f32x2 register pair.
//   - single fused pack kernel (src->fp16 planes, cur->float4 planes).

namespace cvk {

constexpr int S = 8, C = 16, H = 64, W = 96, D = 64, N = H * W;
constexpr int SRC_PACK_BLOCKS = (S * N * 4) / 256;   // 768
constexpr int CUR_PACK_BLOCKS = (N * 4) / 256;       // 96

// Static device scratch (no allocation).
__device__ uint4  g_srcA[S * N];   // fp16 ch0..7  per pixel (4 x half2)
__device__ uint4  g_srcB[S * N];   // fp16 ch8..15 per pixel
__device__ float4 g_cur[4 * N];    // fp32 cur feats, plane q holds ch 4q..4q+3

// ---------------------------------------------------------------- pack pass
__global__ __launch_bounds__(256)
void pack_all(const float* __restrict__ src, const float* __restrict__ cur) {
    int bid = blockIdx.x;
    if (bid < SRC_PACK_BLOCKS) {
        // idx = h*(S*N) + s*N + n   (n fastest -> coalesced loads)
        int idx = bid * 256 + threadIdx.x;
        int h = idx / (S * N);            // 0..3 : which 4-channel group
        int sn = idx - h * (S * N);       // s*N + n
        int n_local = sn % N;
        int s = sn / N;
        const float* p = src + (size_t)s * C * N + (size_t)(4 * h) * N + n_local;
        __half2 a = __floats2half2_rn(p[0],     p[N]);
        __half2 b = __floats2half2_rn(p[2 * N], p[3 * N]);
        uint2 v;
        v.x = *reinterpret_cast<unsigned*>(&a);
        v.y = *reinterpret_cast<unsigned*>(&b);
        uint2* plane = (h < 2) ? reinterpret_cast<uint2*>(g_srcA)
                               : reinterpret_cast<uint2*>(g_srcB);
        plane[(size_t)sn * 2 + (h & 1)] = v;
    } else {
        int idx = (bid - SRC_PACK_BLOCKS) * 256 + threadIdx.x;  // q*N + n
        int q = idx / N;
        int n = idx - q * N;
        float4 f;
        f.x = cur[(size_t)(4 * q + 0) * N + n];
        f.y = cur[(size_t)(4 * q + 1) * N + n];
        f.z = cur[(size_t)(4 * q + 2) * N + n];
        f.w = cur[(size_t)(4 * q + 3) * N + n];
        g_cur[idx] = f;
    }
}

// ------------------------------------------------------------ packed helpers
__device__ __forceinline__ unsigned long long pack_f2(float lo, float hi) {
    unsigned long long u;
    asm("mov.b64 %0, {%1, %2};" : "=l"(u) : "f"(lo), "f"(hi));
    return u;
}
__device__ __forceinline__ void unpack_f2(unsigned long long u, float& lo, float& hi) {
    asm("mov.b64 {%0, %1}, %2;" : "=f"(lo), "=f"(hi) : "l"(u));
}
__device__ __forceinline__ void fma_f32x2(unsigned long long& d,
                                          unsigned long long a,
                                          unsigned long long b) {
    asm("fma.rn.f32x2 %0, %1, %2, %3;" : "=l"(d) : "l"(a), "l"(b), "l"(d));
}

// Blend 4 taps (one 16B plane = 4 half2) with fp16 weights, then dot the
// blended half2s against packed fp32 cur pairs, accumulating into acc (f32x2).
__device__ __forceinline__ void blend_dot(unsigned long long& acc,
                                          uint4 t00, uint4 t10, uint4 t01, uint4 t11,
                                          __half2 h00, __half2 h10,
                                          __half2 h01, __half2 h11,
                                          const unsigned long long* __restrict__ cfp) {
#pragma unroll
    for (int j = 0; j < 4; j++) {
        __half2 a = *(reinterpret_cast<__half2*>(&t00.x) + j);
        __half2 b = *(reinterpret_cast<__half2*>(&t10.x) + j);
        __half2 c = *(reinterpret_cast<__half2*>(&t01.x) + j);
        __half2 e = *(reinterpret_cast<__half2*>(&t11.x) + j);
        __half2 v = __hmul2(a, h00);
        v = __hfma2(b, h10, v);
        v = __hfma2(c, h01, v);
        v = __hfma2(e, h11, v);
        float2 f = __half22float2(v);
        fma_f32x2(acc, pack_f2(f.x, f.y), cfp[j]);
    }
}

// --------------------------------------------------------------- main kernel
__global__ __launch_bounds__(256)
void cost_main(const float* __restrict__ exts, const float* __restrict__ Ks,
               const float* __restrict__ invK, const float* __restrict__ mnp,
               const float* __restrict__ mxp, float* __restrict__ out) {
    __shared__ float sP[S][12];
    int t = threadIdx.y * 32 + threadIdx.x;
    if (t < S * 12) {
        int s = t / 12, rc = t - 12 * s, r = rc >> 2, c = rc & 3;
        float accm = 0.f;
#pragma unroll
        for (int k = 0; k < 4; k++)
            accm += Ks[s * 16 + r * 4 + k] * exts[s * 16 + k * 4 + c];
        sP[s][rc] = accm;
    }
    __syncthreads();

    int x = blockIdx.x * 32 + threadIdx.x;
    int y = blockIdx.y;
    int d = blockIdx.z * 8 + threadIdx.y;
    int n = y * W + x;

    // Log-spaced depth (linspace(0,1,64) ramp = d/63)
    float mnv = mnp[0], mxv = mxp[0];
    float depth = expf(logf(mnv) + logf(mxv / mnv) * ((float)d * (1.f / 63.f)));

    // Back-projected ray * depth
    float pxc = (float)x + 0.5f, pyc = (float)y + 0.5f;
    float X = depth * (invK[0] * pxc + invK[1] * pyc + invK[2]);
    float Y = depth * (invK[4] * pxc + invK[5] * pyc + invK[6]);
    float Z = depth * (invK[8] * pxc + invK[9] * pyc + invK[10]);

    // Current-frame features, packed as 8 f32x2 pairs.
    unsigned long long cfp[8];
#pragma unroll
    for (int q = 0; q < 4; q++) {
        float4 f = g_cur[q * N + n];
        cfp[2 * q + 0] = pack_f2(f.x, f.y);
        cfp[2 * q + 1] = pack_f2(f.z, f.w);
    }

    unsigned long long acc = 0ull;   // f32x2 accumulator across taps+sources

#pragma unroll
    for (int s = 0; s < S; s++) {
        const float* P = sP[s];
        float pu = P[0] * X + P[1] * Y + P[2]  * Z + P[3];
        float pv = P[4] * X + P[5] * Y + P[6]  * Z + P[7];
        float pz = P[8] * X + P[9] * Y + P[10] * Z + P[11];
        if (pz > 0.f) {                         // mask = (z > 0)
            float iz = 1.f / (pz + 1e-8f);
            float gx = pu * iz - 0.5f;
            float gy = pv * iz - 0.5f;
            float x0f = floorf(gx), y0f = floorf(gy);
            float wx = gx - x0f, wy = gy - y0f;
            int x0 = (int)x0f, y0 = (int)y0f;
            if (x0 >= -1 && x0 <= W - 1 && y0 >= -1 && y0 <= H - 1) {
                // validity folded into weights (grid_sample zeros padding)
                float wx0 = (x0 >= 0)     ? (1.f - wx) : 0.f;
                float wx1 = (x0 < W - 1)  ? wx         : 0.f;
                float wy0 = (y0 >= 0)     ? (1.f - wy) : 0.f;
                float wy1 = (y0 < H - 1)  ? wy         : 0.f;
                __half2 h00 = __float2half2_rn(wx0 * wy0);
                __half2 h10 = __float2half2_rn(wx1 * wy0);
                __half2 h01 = __float2half2_rn(wx0 * wy1);
                __half2 h11 = __float2half2_rn(wx1 * wy1);

                int xc0 = max(x0, 0), xc1 = min(x0 + 1, W - 1);
                int yc0 = max(y0, 0), yc1 = min(y0 + 1, H - 1);
                int base = s * N;
                int i00 = base + yc0 * W + xc0;
                int i10 = base + yc0 * W + xc1;
                int i01 = base + yc1 * W + xc0;
                int i11 = base + yc1 * W + xc1;

                uint4 a00 = g_srcA[i00], a10 = g_srcA[i10];
                uint4 a01 = g_srcA[i01], a11 = g_srcA[i11];
                uint4 b00 = g_srcB[i00], b10 = g_srcB[i10];
                uint4 b01 = g_srcB[i01], b11 = g_srcB[i11];

                blend_dot(acc, a00, a10, a01, a11, h00, h10, h01, h11, cfp + 0);
                blend_dot(acc, b00, b10, b01, b11, h00, h10, h01, h11, cfp + 4);
            }
        }
    }

    float lo, hi;
    unpack_f2(acc, lo, hi);
    out[d * N + n] = lo + hi;            // cost_volume [D,H,W]
    out[D * N + d * N + n] = depth;      // depth_planes [D,H,W]
}

}  // namespace cvk

extern "C" void kernel_launch(void* const* d_in, const int* in_sizes, int n_in,
                              void* d_out, int out_size) {
    using namespace cvk;
    const float* cur  = (const float*)d_in[0];  // [1,16,64,96]
    const float* src  = (const float*)d_in[1];  // [1,8,16,64,96]
    const float* exts = (const float*)d_in[2];  // [1,8,4,4]
    const float* Ks   = (const float*)d_in[3];  // [1,8,4,4]
    const float* invK = (const float*)d_in[4];  // [1,4,4]
    const float* mnp  = (const float*)d_in[5];  // [1,1,1,1]
    const float* mxp  = (const float*)d_in[6];  // [1,1,1,1]
    float* out = (float*)d_out;

    pack_all<<<SRC_PACK_BLOCKS + CUR_PACK_BLOCKS, 256>>>(src, cur);

    dim3 blk(32, 8);
    dim3 grd(W / 32, H, D / 8);
    cost_main<<<grd, blk>>>(exts, Ks, invK, mnp, mxp, out);
}